// round 12
// baseline (speedup 1.0000x reference)
#include <cuda_runtime.h>
#include <cuda_fp16.h>

#define NN 100000
#define EE 1000000
#define HH 64
#define GG 512
#define CC 2

#define SCAN_T 512
#define SCAN_NB ((NN + SCAN_T - 1) / SCAN_T)   // 196
#define FIXS 16777216.0f                       // 2^24 fixed-point scale
#define FIXMASK ((1ull << 44) - 1)

// Scratch (device globals; no allocations allowed)
__device__ __half g_bufA[NN * HH];
__device__ __half g_bufB[NN * HH];
__device__ float g_y[NN * CC];
__device__ float g_dinv[NN];
__device__ unsigned long long g_degcnt[NN];   // count<<44 | wsum*2^24
__device__ int   g_fill[NN];
__device__ int   g_rowptr[NN + 1];
__device__ int2  g_cmeta[EE];                 // (src, norm bits)
__device__ float g_cnt[GG];
__device__ float g_plog[GG * CC];
__device__ float g_M[HH * CC];                // W3 @ Wl
__device__ float g_bWl[CC];                   // b3 @ Wl
__device__ int   g_bsum[SCAN_NB];
__device__ int   g_boff[SCAN_NB];

// ---------------------------------------------------------------------------
__global__ __launch_bounds__(256) void k_zero(const float* __restrict__ W3,
                                              const float* __restrict__ Wl,
                                              const float* __restrict__ b3) {
    int i = blockIdx.x * blockDim.x + threadIdx.x;
    if (i < NN) { g_degcnt[i] = 0ull; g_fill[i] = 0; }
    if (i < GG) g_cnt[i] = 0.f;
    if (i < GG * CC) g_plog[i] = 0.f;
    if (blockIdx.x == 0) {
        int t = threadIdx.x;
        if (t < HH * CC) {
            int k = t >> 1, c = t & 1;
            float acc = 0.f;
#pragma unroll
            for (int j = 0; j < HH; j++) acc += W3[k * HH + j] * Wl[j * CC + c];
            g_M[t] = acc;
        } else if (t < HH * CC + CC) {
            int c = t - HH * CC;
            float acc = 0.f;
#pragma unroll
            for (int j = 0; j < HH; j++) acc += b3[j] * Wl[j * CC + c];
            g_bWl[c] = acc;
        }
    }
}

// degree pass: one packed 64-bit atomic per edge
__global__ __launch_bounds__(256) void k_deg(const int* __restrict__ dst,
                                             const float* __restrict__ w) {
    int e = blockIdx.x * blockDim.x + threadIdx.x;
    if (e < EE) {
        unsigned long long val =
            (1ull << 44) | (unsigned long long)(w[e] * FIXS);
        atomicAdd(&g_degcnt[dst[e]], val);
    }
}

// scanA + dinv + graph node count (fused)
__global__ __launch_bounds__(SCAN_T) void k_scanA(const int* __restrict__ batch) {
    __shared__ int sh[SCAN_T / 32];
    int b = blockIdx.x, t = threadIdx.x;
    int i = b * SCAN_T + t;
    unsigned long long pv = (i < NN) ? g_degcnt[i] : 0ull;
    int v = (int)(pv >> 44);
    if (i < NN) {
        float deg = (float)((double)(pv & FIXMASK) * (1.0 / 16777216.0));
        g_dinv[i] = rsqrtf(deg + 2.0f);
        atomicAdd(&g_cnt[batch[i]], 1.0f);
    }
    int s = v;
#pragma unroll
    for (int off = 16; off; off >>= 1) s += __shfl_xor_sync(~0u, s, off);
    if ((t & 31) == 0) sh[t >> 5] = s;
    __syncthreads();
    if (t < SCAN_T / 32) {
        int r = sh[t];
#pragma unroll
        for (int off = SCAN_T / 64; off; off >>= 1)
            r += __shfl_xor_sync(0xffffu, r, off);
        if (t == 0) g_bsum[b] = r;
    }
}

__global__ __launch_bounds__(256) void k_scanB() {
    __shared__ int sh[256];
    int t = threadIdx.x;
    int v = (t < SCAN_NB) ? g_bsum[t] : 0;
    sh[t] = v;
    __syncthreads();
    for (int off = 1; off < 256; off <<= 1) {
        int u = (t >= off) ? sh[t - off] : 0;
        __syncthreads();
        sh[t] += u;
        __syncthreads();
    }
    if (t < SCAN_NB) g_boff[t] = sh[t] - v;
    if (t == 255) g_rowptr[NN] = sh[255];
}

__global__ __launch_bounds__(SCAN_T) void k_scanC() {
    __shared__ int sh[SCAN_T];
    int b = blockIdx.x, t = threadIdx.x;
    int i = b * SCAN_T + t;
    int v = (i < NN) ? (int)(g_degcnt[i] >> 44) : 0;
    sh[t] = v;
    __syncthreads();
    for (int off = 1; off < SCAN_T; off <<= 1) {
        int u = (t >= off) ? sh[t - off] : 0;
        __syncthreads();
        sh[t] += u;
        __syncthreads();
    }
    if (i < NN) g_rowptr[i] = g_boff[b] + sh[t] - v;
}

__global__ __launch_bounds__(256) void k_fill(const int* __restrict__ src,
                                              const int* __restrict__ dst,
                                              const float* __restrict__ w) {
    int e = blockIdx.x * blockDim.x + threadIdx.x;
    if (e < EE) {
        int s = src[e], d = dst[e];
        float nrm = g_dinv[s] * w[e] * g_dinv[d];
        int pos = g_rowptr[d] + atomicAdd(&g_fill[d], 1);
        g_cmeta[pos] = make_int2(s, __float_as_int(nrm));
    }
}

// ---------------------------------------------------------------------------
// accumulate 4 halves (as float2 bits) scaled by v into A[0..3]
__device__ __forceinline__ void h4acc(float2 r, float v, float* A) {
    __half2* hp = (__half2*)&r;
    float2 lo = __half22float2(hp[0]);
    float2 hi = __half22float2(hp[1]);
    A[0] += v * lo.x; A[1] += v * lo.y; A[2] += v * hi.x; A[3] += v * hi.y;
}

// Warp gather: 2 edges concurrently (lane bit4 = edge-of-pair), 16 lanes x 4
// cols each.  Result a[0..3] = aggregated cols sub*4..sub*4+3 (valid all lanes).
__device__ __forceinline__ void gather_node4(const __half* __restrict__ xw,
                                             int n, int lane,
                                             const float* __restrict__ bias,
                                             float* a) {
    int sub = lane & 15;
    int half = lane >> 4;
    int beg = g_rowptr[n], end = g_rowptr[n + 1];
    float A0[4] = {}, A1[4] = {}, A2[4] = {}, A3[4] = {};
    for (int cb = beg; cb < end; cb += 32) {
        int m = end - cb; if (m > 32) m = 32;
        int sreg = 0; float vreg = 0.f;
        if (lane < m) {
            int2 mv = g_cmeta[cb + lane];
            sreg = mv.x; vreg = __int_as_float(mv.y);
        }
        for (int j = 0; j < m; j += 8) {          // 4 pairs = 8 edges / iter
            int i0 = j + half, i1 = j + 2 + half, i2 = j + 4 + half, i3 = j + 6 + half;
            int s0 = __shfl_sync(~0u, sreg, i0); float v0 = __shfl_sync(~0u, vreg, i0);
            int s1 = __shfl_sync(~0u, sreg, i1); float v1 = __shfl_sync(~0u, vreg, i1);
            int s2 = __shfl_sync(~0u, sreg, i2); float v2 = __shfl_sync(~0u, vreg, i2);
            int s3 = __shfl_sync(~0u, sreg, i3); float v3 = __shfl_sync(~0u, vreg, i3);
            float2 r0 = *(const float2*)(xw + (size_t)s0 * 64 + sub * 4);
            float2 r1 = *(const float2*)(xw + (size_t)s1 * 64 + sub * 4);
            float2 r2 = *(const float2*)(xw + (size_t)s2 * 64 + sub * 4);
            float2 r3 = *(const float2*)(xw + (size_t)s3 * 64 + sub * 4);
            h4acc(r0, v0, A0); h4acc(r1, v1, A1);
            h4acc(r2, v2, A2); h4acc(r3, v3, A3);
        }
    }
#pragma unroll
    for (int c = 0; c < 4; c++) {
        float s = (A0[c] + A1[c]) + (A2[c] + A3[c]);
        s += __shfl_xor_sync(~0u, s, 16);          // merge pair halves
        a[c] = s;
    }
    float di = g_dinv[n];
    float sl = 2.0f * di * di;
    float2 xn = *(const float2*)(xw + (size_t)n * 64 + sub * 4);
    __half2* hp = (__half2*)&xn;
    float2 lo = __half22float2(hp[0]);
    float2 hi = __half22float2(hp[1]);
    float4 bb = *(const float4*)(bias + sub * 4);
    a[0] += sl * lo.x + bb.x;
    a[1] += sl * lo.y + bb.y;
    a[2] += sl * hi.x + bb.z;
    a[3] += sl * hi.y + bb.w;
}

__device__ __forceinline__ void store_h4(__half* __restrict__ out, size_t off,
                                         float a, float b, float c, float d) {
    __half2 h01 = __floats2half2_rn(a, b);
    __half2 h23 = __floats2half2_rn(c, d);
    uint2 pk;
    pk.x = *reinterpret_cast<unsigned*>(&h01);
    pk.y = *reinterpret_cast<unsigned*>(&h23);
    *reinterpret_cast<uint2*>(out + off) = pk;
}

// ---------------------------------------------------------------------------
// Layer-1 GEMM: out(fp16) = in @ W.
__global__ __launch_bounds__(256) void k_gemm64(const float* __restrict__ in,
                                                const float* __restrict__ W,
                                                __half* __restrict__ out) {
    __shared__ float Ws[64 * 64];
    __shared__ float XsT[64][65];
    int tid = threadIdx.x;
    int base = blockIdx.x * 64;
    for (int i = tid; i < 4096; i += 256) Ws[i] = W[i];
    for (int idx = tid; idx < 4096; idx += 256) {
        int r = idx >> 6, c = idx & 63;
        int row = base + r;
        XsT[c][r] = (row < NN) ? in[row * 64 + c] : 0.f;
    }
    __syncthreads();
    int tr = tid >> 4, tc = tid & 15;
    float acc[4][4] = {};
#pragma unroll
    for (int k = 0; k < 64; k++) {
        float x0 = XsT[k][tr * 4 + 0];
        float x1 = XsT[k][tr * 4 + 1];
        float x2 = XsT[k][tr * 4 + 2];
        float x3 = XsT[k][tr * 4 + 3];
        float4 wv = *(const float4*)&Ws[k * 64 + tc * 4];
        acc[0][0] += x0 * wv.x; acc[0][1] += x0 * wv.y;
        acc[0][2] += x0 * wv.z; acc[0][3] += x0 * wv.w;
        acc[1][0] += x1 * wv.x; acc[1][1] += x1 * wv.y;
        acc[1][2] += x1 * wv.z; acc[1][3] += x1 * wv.w;
        acc[2][0] += x2 * wv.x; acc[2][1] += x2 * wv.y;
        acc[2][2] += x2 * wv.z; acc[2][3] += x2 * wv.w;
        acc[3][0] += x3 * wv.x; acc[3][1] += x3 * wv.y;
        acc[3][2] += x3 * wv.z; acc[3][3] += x3 * wv.w;
    }
#pragma unroll
    for (int i = 0; i < 4; i++) {
        int row = base + tr * 4 + i;
        if (row < NN)
            store_h4(out, (size_t)row * 64 + tc * 4,
                     acc[i][0], acc[i][1], acc[i][2], acc[i][3]);
    }
}

// ---------------------------------------------------------------------------
// Fused: h = relu(agg(xw_in)+self+bias); xw_out(fp16) = h @ W.
__global__ __launch_bounds__(256) void k_fused(const __half* __restrict__ xw_in,
                                               __half* __restrict__ xw_out,
                                               const float* __restrict__ bias,
                                               const float* __restrict__ W) {
    __shared__ float Ws[64 * 64];
    __shared__ float XsT[64][65];
    int tid = threadIdx.x;
    int wrp = tid >> 5, lane = tid & 31;
    int sub = lane & 15, half = lane >> 4;
    int base = blockIdx.x * 64;
    for (int i = tid; i < 4096; i += 256) Ws[i] = W[i];
#pragma unroll 1
    for (int i = 0; i < 8; i++) {
        int r = wrp * 8 + i;
        int n = base + r;
        float a[4] = {};
        if (n < NN) gather_node4(xw_in, n, lane, bias, a);
        if (half == 0) {
            XsT[sub * 4 + 0][r] = fmaxf(a[0], 0.f);
            XsT[sub * 4 + 1][r] = fmaxf(a[1], 0.f);
            XsT[sub * 4 + 2][r] = fmaxf(a[2], 0.f);
            XsT[sub * 4 + 3][r] = fmaxf(a[3], 0.f);
        }
    }
    __syncthreads();
    int tr = tid >> 4, tc = tid & 15;
    float acc[4][4] = {};
#pragma unroll
    for (int k = 0; k < 64; k++) {
        float x0 = XsT[k][tr * 4 + 0];
        float x1 = XsT[k][tr * 4 + 1];
        float x2 = XsT[k][tr * 4 + 2];
        float x3 = XsT[k][tr * 4 + 3];
        float4 wv = *(const float4*)&Ws[k * 64 + tc * 4];
        acc[0][0] += x0 * wv.x; acc[0][1] += x0 * wv.y;
        acc[0][2] += x0 * wv.z; acc[0][3] += x0 * wv.w;
        acc[1][0] += x1 * wv.x; acc[1][1] += x1 * wv.y;
        acc[1][2] += x1 * wv.z; acc[1][3] += x1 * wv.w;
        acc[2][0] += x2 * wv.x; acc[2][1] += x2 * wv.y;
        acc[2][2] += x2 * wv.z; acc[2][3] += x2 * wv.w;
        acc[3][0] += x3 * wv.x; acc[3][1] += x3 * wv.y;
        acc[3][2] += x3 * wv.z; acc[3][3] += x3 * wv.w;
    }
#pragma unroll
    for (int i = 0; i < 4; i++) {
        int row = base + tr * 4 + i;
        if (row < NN)
            store_h4(xw_out, (size_t)row * 64 + tc * 4,
                     acc[i][0], acc[i][1], acc[i][2], acc[i][3]);
    }
}

// ---------------------------------------------------------------------------
// Layer-3 reduced: h2 = relu(agg+self+b2); y = h2 @ M (64x2)
__global__ __launch_bounds__(256) void k_fused_y(const __half* __restrict__ xw_in,
                                                 const float* __restrict__ bias) {
    int wid = (blockIdx.x * blockDim.x + threadIdx.x) >> 5;
    int lane = threadIdx.x & 31;
    if (wid >= NN) return;
    float a[4];
    gather_node4(xw_in, wid, lane, bias, a);
    int sub = lane & 15;
    int j = sub * 4;
    float y0 = 0.f, y1 = 0.f;
#pragma unroll
    for (int c = 0; c < 4; c++) {
        float h = fmaxf(a[c], 0.f);
        y0 += h * g_M[(j + c) * CC + 0];
        y1 += h * g_M[(j + c) * CC + 1];
    }
#pragma unroll
    for (int off = 8; off; off >>= 1) {
        y0 += __shfl_xor_sync(0xffffffffu, y0, off);
        y1 += __shfl_xor_sync(0xffffffffu, y1, off);
    }
    if (lane == 0) *(float2*)&g_y[wid * CC] = make_float2(y0, y1);
}

// ---------------------------------------------------------------------------
// Edge pass in y-space + pool.
__global__ __launch_bounds__(256) void k_edge(const int* __restrict__ batch) {
    int wid = (blockIdx.x * blockDim.x + threadIdx.x) >> 5;
    int lane = threadIdx.x & 31;
    if (wid >= NN) return;
    int n = wid;
    int beg = g_rowptr[n], end = g_rowptr[n + 1];
    float l0 = 0.f, l1 = 0.f;
    for (int cb = beg + lane; cb < end; cb += 32) {
        int2 mv = g_cmeta[cb];
        float v = __int_as_float(mv.y);
        float2 yv = *(const float2*)&g_y[mv.x * CC];
        l0 += v * yv.x;
        l1 += v * yv.y;
    }
#pragma unroll
    for (int off = 16; off; off >>= 1) {
        l0 += __shfl_xor_sync(0xffffffffu, l0, off);
        l1 += __shfl_xor_sync(0xffffffffu, l1, off);
    }
    if (lane == 0) {
        float di = g_dinv[n];
        float sl = 2.0f * di * di;
        float2 yn = *(const float2*)&g_y[n * CC];
        l0 += sl * yn.x;
        l1 += sl * yn.y;
        int g = batch[n];
        atomicAdd(&g_plog[g * CC + 0], l0);
        atomicAdd(&g_plog[g * CC + 1], l1);
    }
}

__global__ __launch_bounds__(256) void k_final(const float* __restrict__ bl,
                                               float* __restrict__ out) {
    int i = blockIdx.x * blockDim.x + threadIdx.x;
    if (i < GG * CC) {
        int g = i / CC, c = i % CC;
        float cnt = g_cnt[g];
        out[i] = (cnt > 0.f) ? g_plog[i] / cnt + g_bWl[c] + bl[c] : bl[c];
    }
}

extern "C" void kernel_launch(void* const* d_in, const int* in_sizes, int n_in,
                              void* d_out, int out_size) {
    const float* x     = (const float*)d_in[0];
    const int*   ei    = (const int*)d_in[1];
    const float* w     = (const float*)d_in[2];
    const int*   batch = (const int*)d_in[3];
    const float* W1    = (const float*)d_in[4];
    const float* b1    = (const float*)d_in[5];
    const float* W2    = (const float*)d_in[6];
    const float* b2    = (const float*)d_in[7];
    const float* W3    = (const float*)d_in[8];
    const float* b3    = (const float*)d_in[9];
    const float* Wl    = (const float*)d_in[10];
    const float* bl    = (const float*)d_in[11];
    float* out = (float*)d_out;

    const int* src = ei;
    const int* dst = ei + EE;

    __half* A;  cudaGetSymbolAddress((void**)&A, g_bufA);
    __half* B;  cudaGetSymbolAddress((void**)&B, g_bufB);

    const int eb = (EE + 255) / 256;
    const int nb = (NN + 255) / 256;
    const int gemm_b = (NN + 63) / 64;
    const int warp_b = (NN * 32 + 255) / 256;

    // CSR + normalization build (reused by all 3 layers)
    k_zero<<<nb, 256>>>(W3, Wl, b3);
    k_deg<<<eb, 256>>>(dst, w);
    k_scanA<<<SCAN_NB, SCAN_T>>>(batch);
    k_scanB<<<1, 256>>>();
    k_scanC<<<SCAN_NB, SCAN_T>>>();
    k_fill<<<eb, 256>>>(src, dst, w);

    // layer 1: xw1 = x @ W1 -> A (fp16)
    k_gemm64<<<gemm_b, 256>>>(x, W1, A);
    // layer 2 fused: h1 = relu(agg(A)+b1); xw2 = h1 @ W2 -> B (fp16)
    k_fused<<<gemm_b, 256>>>(A, B, b1, W2);
    // layer 3 reduced: h2 = relu(agg(B)+b2); y = h2 @ (W3@Wl)
    k_fused_y<<<warp_b, 256>>>(B, b2);
    // edge pass in y-space + pool
    k_edge<<<warp_b, 256>>>(batch);

    k_final<<<(GG * CC + 255) / 256, 256>>>(bl, out);
}